// round 5
// baseline (speedup 1.0000x reference)
#include <cuda_runtime.h>
#include <cuda_bf16.h>
#include <cstdint>

#define BN_EPS 1e-5f

// ---------------- scratch (no allocations allowed) ----------------
__device__ float g_x1[200000 * 64];        // conv1 output (N x 64)
__device__ float g_x2[(32768 + 1) * 128];  // conv2 output (M x 128)
__device__ float g_stats[512];             // [sum | sumsq | a | d]

// ---------------- helpers ----------------
static __device__ __forceinline__ void red_add2(float* p, float a, float b) {
    asm volatile("red.global.add.v2.f32 [%0], {%1,%2};"
                 :: "l"(p), "f"(a), "f"(b) : "memory");
}

static __device__ __forceinline__ void mma_bf16(float* d, uint32_t a0, uint32_t a1,
                                                uint32_t a2, uint32_t a3,
                                                uint32_t b0, uint32_t b1) {
    asm volatile(
        "mma.sync.aligned.m16n8k16.row.col.f32.bf16.bf16.f32 "
        "{%0,%1,%2,%3}, {%4,%5,%6,%7}, {%8,%9}, {%0,%1,%2,%3};"
        : "+f"(d[0]), "+f"(d[1]), "+f"(d[2]), "+f"(d[3])
        : "r"(a0), "r"(a1), "r"(a2), "r"(a3), "r"(b0), "r"(b1));
}

// ============================================================================
// Sparse conv: gather + bf16 split -> warp mma.sync (3-term) -> red scatter.
// Grid (X, 27). Block 256 threads = 8 warps; tile = 128 pairs; warp = 16 pairs.
// A smem [128][2*CIN+8] bf16 (hi | lo). B smem [COUT][2*CIN+8] = W^T (hi | lo).
// D = Ah*Bh + Ah*Bl + Al*Bh accumulated fp32 in registers.
// Pad rows: gather from row 0 (always in-bounds); their D rows are never
// scattered, so their A content is irrelevant -> no predicated OOB loads.
// ============================================================================
template <int CIN, int COUT>
__global__ __launch_bounds__(256)
void conv_mma(const float* __restrict__ fin, const float* __restrict__ W,
              const int* __restrict__ rin, const int* __restrict__ rout,
              float* __restrict__ out, int P, int n_in) {
    constexpr int SA = 2 * CIN + 8;   // bf16 stride (conflict-free: SA/2 % 32 == 4)
    constexpr int NT = COUT / 8;      // n8 tiles
    constexpr int KS = CIN / 16;      // k16 steps per term

    extern __shared__ __nv_bfloat16 smem_bf[];
    __nv_bfloat16* As = smem_bf;              // 128 * SA
    __nv_bfloat16* Bs = smem_bf + 128 * SA;   // COUT * SA
    __shared__ int s_in[128], s_out[128];

    const int tid = threadIdx.x;
    const int k = blockIdx.y;

    // ---- convert W_k -> Bs (once per block): Bs[cout][cin]=hi, [cout][CIN+cin]=lo
    const float* Wk = W + (size_t)k * CIN * COUT;
    for (int idx = tid; idx < CIN * COUT; idx += 256) {
        int cin = idx / COUT, cout = idx - cin * COUT;
        float w = Wk[idx];
        __nv_bfloat16 h = __float2bfloat16(w);
        __nv_bfloat16 l = __float2bfloat16(w - __bfloat162float(h));
        Bs[cout * SA + cin] = h;
        Bs[cout * SA + CIN + cin] = l;
    }

    const int lane = tid & 31, wid = tid >> 5;
    const int g = lane >> 2, q = lane & 3;    // groupID, quad
    const int wp0 = wid * 16;                 // warp's first pair row
    const int rbase = k * P;
    const int ntiles = (P + 127) >> 7;

    for (int t = blockIdx.x; t < ntiles; t += gridDim.x) {
        {
            int idx = (t << 7) + tid;
            if (tid < 128) {
                s_in[tid] = (idx < P) ? rin[rbase + idx] : n_in;
                s_out[tid] = (idx < P) ? rout[rbase + idx] : 0;
            }
        }
        __syncthreads();
        if (s_in[0] == n_in) break;   // pads trail: this and all later tiles dead

        // ---- gather + split: 2 threads per pair row (clamped, always in-bounds)
        {
            int row = tid >> 1, half = tid & 1;
            int src_row = s_in[row];
            if (src_row == n_in) src_row = 0;   // pad row: content irrelevant
            const float4* src =
                (const float4*)(fin + (size_t)src_row * CIN + half * (CIN / 2));
            __nv_bfloat16* da = As + row * SA + half * (CIN / 2);
#pragma unroll
            for (int j = 0; j < CIN / 8; j++) {
                float4 vv = src[j];
                __nv_bfloat16 hx = __float2bfloat16(vv.x), hy = __float2bfloat16(vv.y);
                __nv_bfloat16 hz = __float2bfloat16(vv.z), hw = __float2bfloat16(vv.w);
                __nv_bfloat162 h01 = __halves2bfloat162(hx, hy);
                __nv_bfloat162 h23 = __halves2bfloat162(hz, hw);
                __nv_bfloat162 l01 = __halves2bfloat162(
                    __float2bfloat16(vv.x - __bfloat162float(hx)),
                    __float2bfloat16(vv.y - __bfloat162float(hy)));
                __nv_bfloat162 l23 = __halves2bfloat162(
                    __float2bfloat16(vv.z - __bfloat162float(hz)),
                    __float2bfloat16(vv.w - __bfloat162float(hw)));
                *(uint2*)(da + 4 * j) =
                    make_uint2(*(uint32_t*)&h01, *(uint32_t*)&h23);
                *(uint2*)(da + CIN + 4 * j) =
                    make_uint2(*(uint32_t*)&l01, *(uint32_t*)&l23);
            }
        }
        __syncthreads();

        // ---- MMA: 3 terms x KS k-steps x NT n-tiles ----
        float d[NT][4];
#pragma unroll
        for (int n = 0; n < NT; n++) {
            d[n][0] = 0.f; d[n][1] = 0.f; d[n][2] = 0.f; d[n][3] = 0.f;
        }
        const __nv_bfloat16* A0 = As + (wp0 + g) * SA + q * 2;
        const __nv_bfloat16* B0 = Bs + g * SA + q * 2;
#pragma unroll
        for (int term = 0; term < 3; term++) {
            const int ka0 = (term == 2) ? CIN : 0;
            const int kb0 = (term == 1) ? CIN : 0;
#pragma unroll 1
            for (int s = 0; s < KS; s++) {
                const int ka = ka0 + s * 16;
                const int kb = kb0 + s * 16;
                uint32_t a0 = *(const uint32_t*)(A0 + ka);
                uint32_t a1 = *(const uint32_t*)(A0 + 8 * SA + ka);
                uint32_t a2 = *(const uint32_t*)(A0 + ka + 8);
                uint32_t a3 = *(const uint32_t*)(A0 + 8 * SA + ka + 8);
                const __nv_bfloat16* bp = B0 + kb;
#pragma unroll
                for (int n = 0; n < NT; n++) {
                    uint32_t b0 = *(const uint32_t*)(bp);
                    uint32_t b1 = *(const uint32_t*)(bp + 8);
                    mma_bf16(d[n], a0, a1, a2, a3, b0, b1);
                    bp += 8 * SA;
                }
            }
        }

        // ---- scatter: rows wp0+g and wp0+g+8, cols q*2 + n*8 ----
        {
            int r0 = wp0 + g, r1 = r0 + 8;
            bool v0 = (s_in[r0] != n_in), v1 = (s_in[r1] != n_in);
            float* dst0 = out + (size_t)s_out[r0] * COUT + q * 2;
            float* dst1 = out + (size_t)s_out[r1] * COUT + q * 2;
#pragma unroll
            for (int n = 0; n < NT; n++) {
                if (v0) red_add2(dst0 + n * 8, d[n][0], d[n][1]);
                if (v1) red_add2(dst1 + n * 8, d[n][2], d[n][3]);
            }
        }
        __syncthreads();
    }
}

// ---------------- BatchNorm (training stats) + ReLU ----------------
template <int COUT>
__global__ void bn_stats(const float* __restrict__ x, int R, float* __restrict__ st) {
    __shared__ float ss[COUT], sq[COUT];
    int tid = threadIdx.x;
    if (tid < COUT) { ss[tid] = 0.f; sq[tid] = 0.f; }
    __syncthreads();
    int c = tid & (COUT - 1);
    constexpr int RPB = 256 / COUT;
    float s = 0.f, qq = 0.f;
    for (int r = blockIdx.x * RPB + tid / COUT; r < R; r += gridDim.x * RPB) {
        float v = x[(size_t)r * COUT + c];
        s += v;
        qq += v * v;
    }
    atomicAdd(&ss[c], s);
    atomicAdd(&sq[c], qq);
    __syncthreads();
    if (tid < COUT) {
        atomicAdd(&st[tid], ss[tid]);
        atomicAdd(&st[COUT + tid], sq[tid]);
    }
}

template <int COUT>
__global__ void bn_finalize(const float* __restrict__ g, const float* __restrict__ b,
                            float invR, float* __restrict__ st) {
    int c = threadIdx.x;
    if (c < COUT) {
        float mu = st[c] * invR;
        float var = st[COUT + c] * invR - mu * mu;
        float a = rsqrtf(var + BN_EPS) * g[c];
        st[2 * COUT + c] = a;
        st[3 * COUT + c] = b[c] - mu * a;
    }
}

template <int COUT>
__global__ void bn_apply_relu(float* __restrict__ x, int total4,
                              const float* __restrict__ st) {
    int i = blockIdx.x * blockDim.x + threadIdx.x;
    if (i >= total4) return;
    float4 v = reinterpret_cast<float4*>(x)[i];
    int c0 = (i * 4) & (COUT - 1);
    const float* A = st + 2 * COUT;
    const float* D = st + 3 * COUT;
    v.x = fmaxf(fmaf(v.x, A[c0 + 0], D[c0 + 0]), 0.f);
    v.y = fmaxf(fmaf(v.y, A[c0 + 1], D[c0 + 1]), 0.f);
    v.z = fmaxf(fmaf(v.z, A[c0 + 2], D[c0 + 2]), 0.f);
    v.w = fmaxf(fmaf(v.w, A[c0 + 3], D[c0 + 3]), 0.f);
    reinterpret_cast<float4*>(x)[i] = v;
}

// ---------------- launch ----------------
extern "C" void kernel_launch(void* const* d_in, const int* in_sizes, int n_in,
                              void* d_out, int out_size) {
    const float* feats = (const float*)d_in[0];
    const float* W1 = (const float*)d_in[1];
    const float* W2 = (const float*)d_in[2];
    const float* W3 = (const float*)d_in[3];
    const float* g1 = (const float*)d_in[4];
    const float* b1 = (const float*)d_in[5];
    const float* g2 = (const float*)d_in[6];
    const float* b2 = (const float*)d_in[7];
    const float* g3 = (const float*)d_in[8];
    const float* b3 = (const float*)d_in[9];
    const int* rb1i = (const int*)d_in[10];
    const int* rb1o = (const int*)d_in[11];
    const int* rb2i = (const int*)d_in[12];
    const int* rb2o = (const int*)d_in[13];
    const int* rb3i = (const int*)d_in[14];
    const int* rb3o = (const int*)d_in[15];

    const int N = in_sizes[0] / 64;
    const int M = out_size / 128;
    const int P1 = in_sizes[10] / 27;
    const int P2 = in_sizes[12] / 27;
    const int P3 = in_sizes[14] / 27;

    float *x1, *x2, *st;
    cudaGetSymbolAddress((void**)&x1, g_x1);
    cudaGetSymbolAddress((void**)&x2, g_x2);
    cudaGetSymbolAddress((void**)&st, g_stats);
    float* out = (float*)d_out;

    // dynamic smem: (128 + COUT) * (2*CIN+8) bf16
    const int smem1 = (128 + 64) * (2 * 64 + 8) * 2;    // 52224
    const int smem2 = (128 + 128) * (2 * 64 + 8) * 2;   // 69632
    const int smem3 = (128 + 128) * (2 * 128 + 8) * 2;  // 135168
    cudaFuncSetAttribute(conv_mma<64, 64>, cudaFuncAttributeMaxDynamicSharedMemorySize, smem1);
    cudaFuncSetAttribute(conv_mma<64, 128>, cudaFuncAttributeMaxDynamicSharedMemorySize, smem2);
    cudaFuncSetAttribute(conv_mma<128, 128>, cudaFuncAttributeMaxDynamicSharedMemorySize, smem3);

    // ---- stage 1: submanifold conv (N x 64) ----
    cudaMemsetAsync(x1, 0, (size_t)N * 64 * sizeof(float), 0);
    conv_mma<64, 64><<<dim3(16, 27), 256, smem1, 0>>>(feats, W1, rb1i, rb1o, x1, P1, N);
    cudaMemsetAsync(st, 0, 512 * sizeof(float), 0);
    bn_stats<64><<<148, 256, 0, 0>>>(x1, N, st);
    bn_finalize<64><<<1, 64, 0, 0>>>(g1, b1, 1.f / (float)N, st);
    {
        int tot4 = N * 64 / 4;
        bn_apply_relu<64><<<(tot4 + 255) / 256, 256, 0, 0>>>(x1, tot4, st);
    }

    // ---- stage 2: stride-2 conv (M x 128) ----
    cudaMemsetAsync(x2, 0, (size_t)M * 128 * sizeof(float), 0);
    conv_mma<64, 128><<<dim3(8, 27), 256, smem2, 0>>>(x1, W2, rb2i, rb2o, x2, P2, N);
    cudaMemsetAsync(st, 0, 512 * sizeof(float), 0);
    bn_stats<128><<<148, 256, 0, 0>>>(x2, M, st);
    bn_finalize<128><<<1, 128, 0, 0>>>(g2, b2, 1.f / (float)M, st);
    {
        int tot4 = M * 128 / 4;
        bn_apply_relu<128><<<(tot4 + 255) / 256, 256, 0, 0>>>(x2, tot4, st);
    }

    // ---- stage 3: submanifold conv on 32^3 grid (M x 128) -> d_out ----
    cudaMemsetAsync(out, 0, (size_t)M * 128 * sizeof(float), 0);
    conv_mma<128, 128><<<dim3(5, 27), 256, smem3, 0>>>(x2, W3, rb3i, rb3o, out, P3, M);
    cudaMemsetAsync(st, 0, 512 * sizeof(float), 0);
    bn_stats<128><<<148, 256, 0, 0>>>(out, M, st);
    bn_finalize<128><<<1, 128, 0, 0>>>(g3, b3, 1.f / (float)M, st);
    {
        int tot4 = M * 128 / 4;
        bn_apply_relu<128><<<(tot4 + 255) / 256, 256, 0, 0>>>(out, tot4, st);
    }
}